// round 5
// baseline (speedup 1.0000x reference)
#include <cuda_runtime.h>

// Problem constants (GNNLayer_64269890617631): x[B,N], edges E
#define BB 64
#define NN 20000
#define EE 1280000

// Scratch: transposed features xt[N][B] and accumulator acc[N][B] (5.12 MB each)
__device__ float g_xt[(size_t)NN * BB];
__device__ float g_acc[(size_t)NN * BB];

#define TILE 32

// Kernel 1: transpose x [B,N] -> xt [N,B], and zero acc.
__global__ void prep_kernel(const float* __restrict__ x, int n_nodes) {
    __shared__ float tile[BB][TILE + 1];
    const int nbase = blockIdx.x * TILE;
    const int tid = threadIdx.x;  // 256 threads

    for (int idx = tid; idx < BB * TILE; idx += 256) {
        const int i = idx / TILE;
        const int n = idx % TILE;
        const int gn = nbase + n;
        tile[i][n] = (gn < n_nodes) ? x[(size_t)i * n_nodes + gn] : 0.0f;
    }
    __syncthreads();
    for (int idx = tid; idx < TILE * BB; idx += 256) {
        const int n = idx / BB;
        const int i = idx % BB;
        const int gn = nbase + n;
        if (gn < n_nodes) {
            g_xt[(size_t)gn * BB + i] = tile[i][n];
            g_acc[(size_t)gn * BB + i] = 0.0f;
        }
    }
}

// Kernel 2: per-edge scatter. 16 threads per edge, float4 per thread.
//   acc[dst][0..63] += (adj[e]*w[e]) * xt[src][0..63]
__global__ void edge_kernel(const float* __restrict__ adj,
                            const float* __restrict__ w,
                            const int* __restrict__ src,
                            const int* __restrict__ dst,
                            int n_edges) {
    const long long t = (long long)blockIdx.x * blockDim.x + threadIdx.x;
    const int e = (int)(t >> 4);
    const int l = (int)(t & 15);
    if (e >= n_edges) return;

    const float coeff = __ldg(&adj[e]) * __ldg(&w[e]);
    const int s = __ldg(&src[e]);
    const int d = __ldg(&dst[e]);

    float4 v = ((const float4*)g_xt)[(size_t)s * (BB / 4) + l];
    v.x *= coeff; v.y *= coeff; v.z *= coeff; v.w *= coeff;

    float* p = g_acc + (size_t)d * BB + l * 4;
    asm volatile("red.global.add.v4.f32 [%0], {%1, %2, %3, %4};"
                 :: "l"(p), "f"(v.x), "f"(v.y), "f"(v.z), "f"(v.w)
                 : "memory");
}

// Kernel 3: out[i][n] = relu(acc[n][i] * (x[0][n]*self_w[n]) + b[n])
__global__ void final_kernel(const float* __restrict__ x,
                             const float* __restrict__ self_w,
                             const float* __restrict__ b,
                             float* __restrict__ out,
                             int n_nodes) {
    __shared__ float tile[TILE][BB + 1];
    __shared__ float sl[TILE];
    __shared__ float bias[TILE];
    const int nbase = blockIdx.x * TILE;
    const int tid = threadIdx.x;  // 256 threads

    if (tid < TILE) {
        const int gn = nbase + tid;
        if (gn < n_nodes) {
            sl[tid] = x[gn] * self_w[gn];  // x row 0 (faithful quirk)
            bias[tid] = b[gn];
        }
    }
    for (int idx = tid; idx < TILE * BB; idx += 256) {
        const int n = idx / BB;
        const int i = idx % BB;
        const int gn = nbase + n;
        if (gn < n_nodes) tile[n][i] = g_acc[(size_t)gn * BB + i];
    }
    __syncthreads();
    for (int idx = tid; idx < BB * TILE; idx += 256) {
        const int i = idx / TILE;
        const int n = idx % TILE;
        const int gn = nbase + n;
        if (gn < n_nodes) {
            const float v = tile[n][i] * sl[n] + bias[n];
            out[(size_t)i * n_nodes + gn] = fmaxf(v, 0.0f);
        }
    }
}

extern "C" void kernel_launch(void* const* d_in, const int* in_sizes, int n_in,
                              void* d_out, int out_size) {
    // metadata order: x, adj_values, w, self_w, b, src, dst
    const float* x      = (const float*)d_in[0];
    const float* adj    = (const float*)d_in[1];
    const float* w      = (const float*)d_in[2];
    const float* self_w = (const float*)d_in[3];
    const float* b      = (const float*)d_in[4];
    const int*   src    = (const int*)d_in[5];
    const int*   dst    = (const int*)d_in[6];
    float* out = (float*)d_out;

    const int n_nodes = in_sizes[3];   // N from self_w
    const int n_edges = in_sizes[1];   // E from adj_values

    const int n_tiles = (n_nodes + TILE - 1) / TILE;
    prep_kernel<<<n_tiles, 256>>>(x, n_nodes);

    const long long total = (long long)n_edges * 16;
    const int blocks = (int)((total + 255) / 256);
    edge_kernel<<<blocks, 256>>>(adj, w, src, dst, n_edges);

    final_kernel<<<n_tiles, 256>>>(x, self_w, b, out, n_nodes);
}